// round 14
// baseline (speedup 1.0000x reference)
#include <cuda_runtime.h>
#include <cuda_bf16.h>

#define NUM_HIST 4

__device__ __forceinline__ float reluf(float x) { return x > 0.0f ? x : 0.0f; }

__device__ __forceinline__ float overlap(float lx, float ly,
                                         float f, float r, float l, float rt) {
    float a = fminf(reluf(f - lx), reluf(r + lx));
    float b = fminf(reluf(l - ly), reluf(rt + ly));
    return fminf(a, b);
}

// Full pair test for one candidate (already-loaded data).
__device__ __forceinline__ bool pair_hit(
    float ex, float ey, float ce, float se,
    float ef, float er, float el, float ert,
    const float* ecx, const float* ecy,
    float nx, float ny, float nyaw,
    float nf, float nr, float nl, float nrt)
{
    float cn, sn;
    sincosf(nyaw, &sn, &cn);

    float A = 0.0f;
#pragma unroll
    for (int c = 0; c < 4; c++) {
        float dx = ecx[c] - nx;
        float dy = ecy[c] - ny;
        float alx =  cn * dx + sn * dy;
        float aly = -sn * dx + cn * dy;
        A = fmaxf(A, overlap(alx, aly, nf, nr, nl, nrt));
    }
    float B = 0.0f;
    {
        const float lx[4] = { nf,  nf, -nr, -nr };
        const float ly[4] = { nl, -nrt, -nrt, nl };
#pragma unroll
        for (int c = 0; c < 4; c++) {
            float cxg = nx + cn * lx[c] - sn * ly[c];
            float cyg = ny + sn * lx[c] + cn * ly[c];
            float dx = cxg - ex;
            float dy = cyg - ey;
            float blx =  ce * dx + se * dy;
            float bly = -se * dx + ce * dy;
            B = fmaxf(B, overlap(blx, bly, ef, er, el, ert));
        }
    }
    return fmaxf(A, B) > 0.0f;
}

// Grid (T, Ne), blockDim 32: one independent warp per (t, e); no smem, no
// barriers (R9 shape). 2-round-trip critical path via EXACT-WIDTH speculation:
// hypothesis "ego sits at the head of its batch and the batch is exactly 64
// wide" is verified with 3 probe loads (batch[ei-1], batch[ei+63],
// batch[ei+64]) whose addresses depend only on ei. Probes, ego data, and the
// 64 candidates [ei, ei+64) all issue in one round-trip. If confirmed, the
// candidate set is exactly the window (no candidate batch[] loads needed).
// Otherwise: exact binary-search + strided-scan fallback (any input shape).
//
// reward[e] folds across the T blocks of ego e via unsigned atomicMin
// (poison 0xAAAAAAAA > 0x3F800000 = 1.0f bits; idempotent across replays).
__global__ void __launch_bounds__(32)
fused_kernel(const float* __restrict__ pos,          // (N, T_TOT, 2)
             const float* __restrict__ yaw,          // (N, T_TOT)
             const unsigned int* __restrict__ msk,   // (N, T_TOT) bool as 32-bit
             const float* __restrict__ box,          // (N, 4)
             const int* __restrict__ batch,          // (N,) sorted
             const int* __restrict__ ego,            // (Ne,)
             float* __restrict__ out,                // [done.T | reward]
             int N, int T_TOT, int T, int Ne)
{
    const int t    = blockIdx.x;
    const int e    = blockIdx.y;
    const int lane = threadIdx.x;
    const int tt   = t + NUM_HIST;

    const int ei = ego[e];                       // RT1

    // ---- RT2: all addresses below depend only on ei ----
    const bool spec = (ei + 64 <= N);

    // Probes for speculation check.
    int b_prev = 0, b_last = 0, b_next = 0;
    if (spec) {
        b_prev = batch[ei > 0 ? ei - 1 : 0];
        b_last = batch[ei + 63];
        b_next = batch[ei + 64 < N ? ei + 64 : N - 1];
    }

    // Speculative candidates: n0 = ei + lane, n1 = ei + 32 + lane.
    unsigned int m0 = 0u, m1 = 0u;
    float        y0 = 0.f, y1 = 0.f;
    float2       p0 = {0.f, 0.f}, p1 = {0.f, 0.f};
    float4       b0 = {0.f, 0.f, 0.f, 0.f}, b1 = {0.f, 0.f, 0.f, 0.f};
    const int n0 = ei + lane;
    const int n1 = ei + 32 + lane;
    if (spec) {
        m0 = msk[n0 * T_TOT + tt];
        y0 = yaw[n0 * T_TOT + tt];
        p0 = ((const float2*)pos)[n0 * T_TOT + tt];
        b0 = ((const float4*)box)[n0];
        m1 = msk[n1 * T_TOT + tt];
        y1 = yaw[n1 * T_TOT + tt];
        p1 = ((const float2*)pos)[n1 * T_TOT + tt];
        b1 = ((const float4*)box)[n1];
    }

    // Ego data (same round-trip).
    const float eyaw = yaw[ei * T_TOT + tt];
    const float2 ep  = ((const float2*)pos)[ei * T_TOT + tt];
    const unsigned int emv = msk[ei * T_TOT + tt];
    const float4 ebx = ((const float4*)box)[ei];
    const int eb = batch[ei];

    const float ex = ep.x, ey = ep.y;
    const float ef = ebx.x, er = ebx.y, el = ebx.z, ert = ebx.w;

    float ce, se;
    sincosf(eyaw, &se, &ce);
    float ecx[4], ecy[4];
    {
        const float lx[4] = { ef,  ef, -er, -er };
        const float ly[4] = { el, -ert, -ert, el };
#pragma unroll
        for (int c = 0; c < 4; c++) {
            ecx[c] = ex + ce * lx[c] - se * ly[c];
            ecy[c] = ey + se * lx[c] + ce * ly[c];
        }
    }

    // Confirm speculation: range is exactly [ei, ei+64).
    const bool confirmed = spec
        && (ei == 0        || b_prev != eb)
        && (b_last == eb)
        && (ei + 64 == N   || b_next != eb);

    int any_edge = 0;
    int any_hit  = 0;

    if (confirmed) {
        if (emv != 0u) {
            const bool va = (m0 != 0u) && (n0 != ei);
            const bool vb = (m1 != 0u) && (n1 != ei);
            any_edge |= (va || vb) ? 1 : 0;
            if (va && pair_hit(ex, ey, ce, se, ef, er, el, ert, ecx, ecy,
                               p0.x, p0.y, y0, b0.x, b0.y, b0.z, b0.w)) any_hit = 1;
            if (vb && pair_hit(ex, ey, ce, se, ef, er, el, ert, ecx, ecy,
                               p1.x, p1.y, y1, b1.x, b1.y, b1.z, b1.w)) any_hit = 1;
        }
    } else if (emv != 0u) {
        // Exact fallback: binary search for [lo, hi), strided scan.
        int a = 0, b = 0;
        if (lane == 0) {
            int L = 0, H = N;
            while (L < H) { int m = (L + H) >> 1; if (batch[m] <  eb) L = m + 1; else H = m; }
            a = L; H = N;
            while (L < H) { int m = (L + H) >> 1; if (batch[m] <= eb) L = m + 1; else H = m; }
            b = L;
        }
        const int lo = __shfl_sync(0xffffffffu, a, 0);
        const int hi = __shfl_sync(0xffffffffu, b, 0);
        for (int n = lo + lane; n < hi; n += 32) {
            const unsigned int nmv = msk[n * T_TOT + tt];
            const float nyaw = yaw[n * T_TOT + tt];
            const float2 p   = ((const float2*)pos)[n * T_TOT + tt];
            const float4 b4  = ((const float4*)box)[n];
            const bool valid = (nmv != 0u) && (n != ei);
            any_edge |= valid ? 1 : 0;
            if (valid && pair_hit(ex, ey, ce, se, ef, er, el, ert, ecx, ecy,
                                  p.x, p.y, nyaw, b4.x, b4.y, b4.z, b4.w))
                any_hit = 1;
        }
    }

    const unsigned be = __ballot_sync(0xffffffffu, any_edge);
    const unsigned bh = __ballot_sync(0xffffffffu, any_hit);
    const int done_t = (be != 0u && bh != 0u) ? 1 : 0;

    if (lane == 0) {
        out[e * T + t] = done_t ? 1.0f : 0.0f;           // done.T layout: [e, t]
        atomicMin((unsigned int*)out + Ne * T + e, done_t ? 0u : 0x3F800000u);
    }
}

extern "C" void kernel_launch(void* const* d_in, const int* in_sizes, int n_in,
                              void* d_out, int out_size)
{
    const float*        pos   = (const float*)d_in[0];         // (N, T_TOT, 2)
    const float*        yaw   = (const float*)d_in[1];         // (N, T_TOT)
    const unsigned int* msk   = (const unsigned int*)d_in[2];  // (N, T_TOT) bool as 32-bit
    const float*        box   = (const float*)d_in[3];         // (N, 4)
    const int*          batch = (const int*)d_in[4];           // (N,)
    const int*          ego   = (const int*)d_in[5];           // (Ne,)
    float*              out   = (float*)d_out;

    const int N     = in_sizes[4];
    const int T_TOT = in_sizes[1] / N;
    const int T     = T_TOT - NUM_HIST;   // 16
    const int Ne    = in_sizes[5];        // 64

    dim3 grid(T, Ne);
    fused_kernel<<<grid, 32>>>(pos, yaw, msk, box, batch, ego, out,
                               N, T_TOT, T, Ne);
}

// round 15
// speedup vs baseline: 1.3029x; 1.3029x over previous
#include <cuda_runtime.h>
#include <cuda_bf16.h>

#define NUM_HIST 4

__device__ __forceinline__ float reluf(float x) { return x > 0.0f ? x : 0.0f; }

__device__ __forceinline__ float overlap(float lx, float ly,
                                         float f, float r, float l, float rt) {
    float a = fminf(reluf(f - lx), reluf(r + lx));
    float b = fminf(reluf(l - ly), reluf(rt + ly));
    return fminf(a, b);
}

// Full pair test for one candidate (already-loaded data).
__device__ __forceinline__ bool pair_hit(
    float ex, float ey, float ce, float se,
    float ef, float er, float el, float ert,
    const float* ecx, const float* ecy,
    float nx, float ny, float nyaw,
    float nf, float nr, float nl, float nrt)
{
    float cn, sn;
    sincosf(nyaw, &sn, &cn);

    float A = 0.0f;
#pragma unroll
    for (int c = 0; c < 4; c++) {
        float dx = ecx[c] - nx;
        float dy = ecy[c] - ny;
        float alx =  cn * dx + sn * dy;
        float aly = -sn * dx + cn * dy;
        A = fmaxf(A, overlap(alx, aly, nf, nr, nl, nrt));
    }
    float B = 0.0f;
    {
        const float lx[4] = { nf,  nf, -nr, -nr };
        const float ly[4] = { nl, -nrt, -nrt, nl };
#pragma unroll
        for (int c = 0; c < 4; c++) {
            float cxg = nx + cn * lx[c] - sn * ly[c];
            float cyg = ny + sn * lx[c] + cn * ly[c];
            float dx = cxg - ex;
            float dy = cyg - ey;
            float blx =  ce * dx + se * dy;
            float bly = -se * dx + ce * dy;
            B = fmaxf(B, overlap(blx, bly, ef, er, el, ert));
        }
    }
    return fmaxf(A, B) > 0.0f;
}

// Grid (T, Ne), blockDim 32: one independent warp per (t, e). No smem, no
// barriers (best-measured R9 structure). Range [lo,hi) of ego's batch found by
// warp-parallel 64-ary search over sorted batch[]: round-1 segment-head probes
// are eb-independent and overlap the ego[e]->batch[ei] load chain; round-2
// resolves both bounds in one round-trip via ballot+popc.
//
// Identity used: done[t,e] == "exists a masked same-batch pair with loss > 0"
// (a hit is itself an edge; no edges -> max_loss = -inf -> not done), so only
// one ballot (any_hit) is needed — has_edge tracking is provably redundant.
//
// reward[e] folds across the T blocks of ego e via unsigned atomicMin
// (poison 0xAAAAAAAA > 0x3F800000 = 1.0f bits; idempotent across replays).
__global__ void __launch_bounds__(32)
fused_kernel(const float* __restrict__ pos,          // (N, T_TOT, 2)
             const float* __restrict__ yaw,          // (N, T_TOT)
             const unsigned int* __restrict__ msk,   // (N, T_TOT) bool as 32-bit
             const float* __restrict__ box,          // (N, 4)
             const int* __restrict__ batch,          // (N,) sorted
             const int* __restrict__ ego,            // (Ne,)
             float* __restrict__ out,                // [done.T | reward]
             int N, int T_TOT, int T, int Ne)
{
    const int t    = blockIdx.x;
    const int e    = blockIdx.y;
    const int lane = threadIdx.x;
    const int tt   = t + NUM_HIST;

    const int ei = ego[e];                       // RT1

    // ---- Round-1 search probes: eb-independent, issue immediately ----
    const int S1 = (N + 63) >> 6;                // 64 segments
    const int i0 = lane, i1 = lane + 32;
    const bool ok0 = (i0 * S1) < N;
    const bool ok1 = (i1 * S1) < N;
    const int  q0 = ok0 ? i0 * S1 : N - 1;
    const int  q1 = ok1 ? i1 * S1 : N - 1;
    const int  v0 = batch[q0];
    const int  v1 = batch[q1];

    // ---- Ego data (depends only on ei): overlaps probe round-trip ----
    const float eyaw = yaw[ei * T_TOT + tt];
    const float2 ep  = ((const float2*)pos)[ei * T_TOT + tt];
    const unsigned int emv = msk[ei * T_TOT + tt];
    const float4 ebx = ((const float4*)box)[ei];
    const int eb = batch[ei];                    // RT2 (concurrent)

    const float ex = ep.x, ey = ep.y;
    const float ef = ebx.x, er = ebx.y, el = ebx.z, ert = ebx.w;

    float ce, se;
    sincosf(eyaw, &se, &ce);
    float ecx[4], ecy[4];
    {
        const float lx[4] = { ef,  ef, -er, -er };
        const float ly[4] = { el, -ert, -ert, el };
#pragma unroll
        for (int c = 0; c < 4; c++) {
            ecx[c] = ex + ce * lx[c] - se * ly[c];
            ecy[c] = ey + se * lx[c] + ce * ly[c];
        }
    }

    // ---- Resolve bounds ----
    int lo, hi;
    if (S1 <= 64) {
        const unsigned bl0 = __ballot_sync(0xffffffffu, ok0 && v0 <  eb);
        const unsigned bl1 = __ballot_sync(0xffffffffu, ok1 && v1 <  eb);
        const unsigned bu0 = __ballot_sync(0xffffffffu, ok0 && v0 <= eb);
        const unsigned bu1 = __ballot_sync(0xffffffffu, ok1 && v1 <= eb);
        const int lbs = __popc(bl0) + __popc(bl1);
        const int ubs = __popc(bu0) + __popc(bu1);
        const int start_l = (lbs > 0) ? (lbs - 1) * S1 : 0;
        const int start_u = (ubs > 0) ? (ubs - 1) * S1 : 0;

        // Round 2: probe S1 (<=64) positions of each boundary segment.
        const int jl0 = start_l + lane,      jl1 = start_l + lane + 32;
        const int ju0 = start_u + lane,      ju1 = start_u + lane + 32;
        const bool wl0 = (lane      < S1) && (jl0 < N);
        const bool wl1 = (lane + 32 < S1) && (jl1 < N);
        const bool wu0 = (lane      < S1) && (ju0 < N);
        const bool wu1 = (lane + 32 < S1) && (ju1 < N);
        const int  wv0 = batch[wl0 ? jl0 : 0];
        const int  wv1 = batch[wl1 ? jl1 : 0];
        const int  wv2 = batch[wu0 ? ju0 : 0];
        const int  wv3 = batch[wu1 ? ju1 : 0];

        const unsigned cl0 = __ballot_sync(0xffffffffu, wl0 && wv0 <  eb);
        const unsigned cl1 = __ballot_sync(0xffffffffu, wl1 && wv1 <  eb);
        const unsigned cu0 = __ballot_sync(0xffffffffu, wu0 && wv2 <= eb);
        const unsigned cu1 = __ballot_sync(0xffffffffu, wu1 && wv3 <= eb);
        lo = start_l + __popc(cl0) + __popc(cl1);
        hi = start_u + __popc(cu0) + __popc(cu1);
    } else {
        // Generic fallback: lane-0 binary search, broadcast.
        int a = 0, b = 0;
        if (lane == 0) {
            int L = 0, H = N;
            while (L < H) { int m = (L + H) >> 1; if (batch[m] <  eb) L = m + 1; else H = m; }
            a = L; H = N;
            while (L < H) { int m = (L + H) >> 1; if (batch[m] <= eb) L = m + 1; else H = m; }
            b = L;
        }
        lo = __shfl_sync(0xffffffffu, a, 0);
        hi = __shfl_sync(0xffffffffu, b, 0);
    }

    int any_hit = 0;

    if (emv != 0u) {
        // Batched iterations 0 & 1 (covers ranges up to 64 in one round-trip).
        const int n0 = lo + lane;
        const int n1 = n0 + 32;
        const int c0 = n0 < hi ? n0 : hi - 1;   // hi > lo always (ei in range)
        const int c1 = n1 < hi ? n1 : hi - 1;

        const unsigned int m0 = msk[c0 * T_TOT + tt];
        const float        y0 = yaw[c0 * T_TOT + tt];
        const float2       p0 = ((const float2*)pos)[c0 * T_TOT + tt];
        const float4       b0 = ((const float4*)box)[c0];
        const unsigned int m1 = msk[c1 * T_TOT + tt];
        const float        y1 = yaw[c1 * T_TOT + tt];
        const float2       p1 = ((const float2*)pos)[c1 * T_TOT + tt];
        const float4       b1 = ((const float4*)box)[c1];

        const bool va = (n0 < hi) && (m0 != 0u) && (n0 != ei);
        const bool vb = (n1 < hi) && (m1 != 0u) && (n1 != ei);

        if (va && pair_hit(ex, ey, ce, se, ef, er, el, ert, ecx, ecy,
                           p0.x, p0.y, y0, b0.x, b0.y, b0.z, b0.w)) any_hit = 1;
        if (vb && pair_hit(ex, ey, ce, se, ef, er, el, ert, ecx, ecy,
                           p1.x, p1.y, y1, b1.x, b1.y, b1.z, b1.w)) any_hit = 1;

        // Residual for larger ranges.
        for (int n = n0 + 64; n < hi; n += 32) {
            const unsigned int nmv = msk[n * T_TOT + tt];
            const float nyaw = yaw[n * T_TOT + tt];
            const float2 p   = ((const float2*)pos)[n * T_TOT + tt];
            const float4 b   = ((const float4*)box)[n];
            const bool valid = (nmv != 0u) && (n != ei);
            if (valid && pair_hit(ex, ey, ce, se, ef, er, el, ert, ecx, ecy,
                                  p.x, p.y, nyaw, b.x, b.y, b.z, b.w)) any_hit = 1;
        }
    }

    // done == any masked same-batch pair with loss > 0 (single ballot).
    const unsigned bh = __ballot_sync(0xffffffffu, any_hit);
    const int done_t = (bh != 0u) ? 1 : 0;

    if (lane == 0) {
        out[e * T + t] = done_t ? 1.0f : 0.0f;           // done.T layout: [e, t]
        atomicMin((unsigned int*)out + Ne * T + e, done_t ? 0u : 0x3F800000u);
    }
}

extern "C" void kernel_launch(void* const* d_in, const int* in_sizes, int n_in,
                              void* d_out, int out_size)
{
    const float*        pos   = (const float*)d_in[0];         // (N, T_TOT, 2)
    const float*        yaw   = (const float*)d_in[1];         // (N, T_TOT)
    const unsigned int* msk   = (const unsigned int*)d_in[2];  // (N, T_TOT) bool as 32-bit
    const float*        box   = (const float*)d_in[3];         // (N, 4)
    const int*          batch = (const int*)d_in[4];           // (N,)
    const int*          ego   = (const int*)d_in[5];           // (Ne,)
    float*              out   = (float*)d_out;

    const int N     = in_sizes[4];
    const int T_TOT = in_sizes[1] / N;
    const int T     = T_TOT - NUM_HIST;   // 16
    const int Ne    = in_sizes[5];        // 64

    dim3 grid(T, Ne);
    fused_kernel<<<grid, 32>>>(pos, yaw, msk, box, batch, ego, out,
                               N, T_TOT, T, Ne);
}